// round 10
// baseline (speedup 1.0000x reference)
#include <cuda_runtime.h>
#include <cstddef>

#define NN 50000
#define EE 800000
#define DD 64
#define CH 512

// warp-wide sum broadcast (butterfly; chains are interleaved at call sites for ILP)
__device__ __forceinline__ float warp_sum(float v) {
    #pragma unroll
    for (int o = 16; o > 0; o >>= 1) v += __shfl_xor_sync(0xffffffffu, v, o);
    return v;
}

// ---------------- static device scratch (no allocations allowed) ----------------
__device__ float g_z[(size_t)EE * DD];     // 204.8 MB edge state (R-CSR slot order, in-place)
__device__ float g_y[NN * DD];
__device__ float g_dx[NN * DD];            // dis[i] * xbar[i]
__device__ float g_S[NN * DD];             // partial (kR) then final S (kC2)
__device__ float g_u[NN * DD];             // dis[i] * xk[i]
__device__ float g_dis[NN];

__device__ int g_adj_ptr[NN + 1];
__device__ int g_adj_cur[NN];
__device__ int g_adj_col[2 * EE];
__device__ int g_r_ptr[NN + 1];
__device__ int g_r_cur[NN];
__device__ int g_r_lst[EE];                // other endpoint (c); edge id == slot index
__device__ int g_c_ptr[NN + 1];
__device__ int g_c_cur[NN];
__device__ int g_c_lst[EE];                // R-slot of that edge
__device__ int g_cnt_adj[NN];
__device__ int g_cnt_r[NN];
__device__ int g_cnt_c[NN];
__device__ int g_part[3 * 128];

// ---------------- precompute ----------------
__global__ void kInit(int n) {
    int i = blockIdx.x * blockDim.x + threadIdx.x;
    if (i < n) { g_cnt_adj[i] = 0; g_cnt_r[i] = 0; g_cnt_c[i] = 0; }
}

__global__ void kCount(const int* __restrict__ src, const int* __restrict__ dst, int ne) {
    int e = blockIdx.x * blockDim.x + threadIdx.x;
    if (e >= ne) return;
    int s = src[e], d = dst[e];
    int r = s > d ? s : d;
    int c = s > d ? d : s;
    atomicAdd(&g_cnt_adj[s], 1);
    atomicAdd(&g_cnt_adj[d], 1);
    atomicAdd(&g_cnt_r[r], 1);
    atomicAdd(&g_cnt_c[c], 1);
}

__global__ void kDis(int n) {
    int i = blockIdx.x * blockDim.x + threadIdx.x;
    if (i >= n) return;
    float x = (float)g_cnt_adj[i] + 1.0f;
    float r = rsqrtf(x);
    r = r * (1.5f - 0.5f * x * r * r);
    g_dis[i] = r;
}

__device__ __forceinline__ const int* cnt_of(int arr) {
    return arr == 0 ? g_cnt_adj : (arr == 1 ? g_cnt_r : g_cnt_c);
}
__device__ __forceinline__ int* ptr_of(int arr) {
    return arr == 0 ? g_adj_ptr : (arr == 1 ? g_r_ptr : g_c_ptr);
}
__device__ __forceinline__ int* cur_of(int arr) {
    return arr == 0 ? g_adj_cur : (arr == 1 ? g_r_cur : g_c_cur);
}

__global__ void kPart(int n) {
    int arr = blockIdx.y;
    int b = blockIdx.x;
    int t = threadIdx.x;
    int i = b * CH + t;
    __shared__ int s[CH];
    s[t] = (i < n) ? cnt_of(arr)[i] : 0;
    __syncthreads();
    for (int off = CH / 2; off > 0; off >>= 1) {
        if (t < off) s[t] += s[t + off];
        __syncthreads();
    }
    if (t == 0) g_part[arr * 128 + b] = s[0];
}

__global__ void kScanPart(int n, int nb) {
    __shared__ int s[384];
    int t = threadIdx.x;
    int arr = t >> 7;
    int i = t & 127;
    int v = (i < nb) ? g_part[arr * 128 + i] : 0;
    s[t] = v;
    __syncthreads();
    for (int off = 1; off < 128; off <<= 1) {
        int u = (i >= off) ? s[t - off] : 0;
        __syncthreads();
        s[t] += u;
        __syncthreads();
    }
    g_part[arr * 128 + i] = s[t] - v;
    if (i == nb - 1) ptr_of(arr)[n] = s[t];
}

__global__ void kWrite(int n) {
    int arr = blockIdx.y;
    int b = blockIdx.x;
    int t = threadIdx.x;
    int i = b * CH + t;
    __shared__ int s[CH];
    int v = (i < n) ? cnt_of(arr)[i] : 0;
    s[t] = v;
    __syncthreads();
    for (int off = 1; off < CH; off <<= 1) {
        int u = (t >= off) ? s[t - off] : 0;
        __syncthreads();
        s[t] += u;
        __syncthreads();
    }
    if (i < n) {
        int excl = s[t] - v + g_part[arr * 128 + b];
        ptr_of(arr)[i] = excl;
        cur_of(arr)[i] = excl;
    }
}

__global__ void kFill(const int* __restrict__ src, const int* __restrict__ dst, int ne) {
    int e = blockIdx.x * blockDim.x + threadIdx.x;
    if (e >= ne) return;
    int s = src[e], d = dst[e];
    int p = atomicAdd(&g_adj_cur[s], 1); g_adj_col[p] = d;
    p = atomicAdd(&g_adj_cur[d], 1);     g_adj_col[p] = s;
    int r = s > d ? s : d;
    int c = s > d ? d : s;
    int slot = atomicAdd(&g_r_cur[r], 1);
    g_r_lst[slot] = c;
    p = atomicAdd(&g_c_cur[c], 1);
    g_c_lst[p] = slot;
}

// ---------------- main loop kernels (warp per row, float2 per lane) ----------------

// A: ax = sum_col u[col] + u[w];  y = 0.25*x0 + 0.75*dis*ax;  xbar = y - 0.25*S;  dx = dis*xbar
__global__ __launch_bounds__(256) void kA(const float* __restrict__ x0, int n, int first) {
    int w = (blockIdx.x * 256 + threadIdx.x) >> 5;
    int lane = threadIdx.x & 31;
    if (w >= n) return;
    int base = g_adj_ptr[w], end = g_adj_ptr[w + 1];
    int ofs = 2 * lane;
    float di = g_dis[w];
    float a0x = 0.f, a0y = 0.f, a1x = 0.f, a1y = 0.f;
    float a2x = 0.f, a2y = 0.f, a3x = 0.f, a3y = 0.f;
    if (first) {
        int e = base;
        for (; e + 3 < end; e += 4) {
            int c0 = __ldg(&g_adj_col[e]);
            int c1 = __ldg(&g_adj_col[e + 1]);
            int c2 = __ldg(&g_adj_col[e + 2]);
            int c3 = __ldg(&g_adj_col[e + 3]);
            float w0 = __ldg(&g_dis[c0]), w1 = __ldg(&g_dis[c1]);
            float w2 = __ldg(&g_dis[c2]), w3 = __ldg(&g_dis[c3]);
            float2 v0 = *reinterpret_cast<const float2*>(x0 + (size_t)c0 * DD + ofs);
            float2 v1 = *reinterpret_cast<const float2*>(x0 + (size_t)c1 * DD + ofs);
            float2 v2 = *reinterpret_cast<const float2*>(x0 + (size_t)c2 * DD + ofs);
            float2 v3 = *reinterpret_cast<const float2*>(x0 + (size_t)c3 * DD + ofs);
            a0x = fmaf(w0, v0.x, a0x); a0y = fmaf(w0, v0.y, a0y);
            a1x = fmaf(w1, v1.x, a1x); a1y = fmaf(w1, v1.y, a1y);
            a2x = fmaf(w2, v2.x, a2x); a2y = fmaf(w2, v2.y, a2y);
            a3x = fmaf(w3, v3.x, a3x); a3y = fmaf(w3, v3.y, a3y);
        }
        for (; e < end; e++) {
            int col = __ldg(&g_adj_col[e]);
            float wt = __ldg(&g_dis[col]);
            float2 v = *reinterpret_cast<const float2*>(x0 + (size_t)col * DD + ofs);
            a0x = fmaf(wt, v.x, a0x); a0y = fmaf(wt, v.y, a0y);
        }
        float2 vs = *reinterpret_cast<const float2*>(x0 + (size_t)w * DD + ofs);
        a0x = fmaf(di, vs.x, a0x); a0y = fmaf(di, vs.y, a0y);
    } else {
        int e = base;
        for (; e + 3 < end; e += 4) {
            int c0 = __ldg(&g_adj_col[e]);
            int c1 = __ldg(&g_adj_col[e + 1]);
            int c2 = __ldg(&g_adj_col[e + 2]);
            int c3 = __ldg(&g_adj_col[e + 3]);
            float2 v0 = *reinterpret_cast<const float2*>(g_u + (size_t)c0 * DD + ofs);
            float2 v1 = *reinterpret_cast<const float2*>(g_u + (size_t)c1 * DD + ofs);
            float2 v2 = *reinterpret_cast<const float2*>(g_u + (size_t)c2 * DD + ofs);
            float2 v3 = *reinterpret_cast<const float2*>(g_u + (size_t)c3 * DD + ofs);
            a0x += v0.x; a0y += v0.y;
            a1x += v1.x; a1y += v1.y;
            a2x += v2.x; a2y += v2.y;
            a3x += v3.x; a3y += v3.y;
        }
        for (; e < end; e++) {
            int col = __ldg(&g_adj_col[e]);
            float2 v = *reinterpret_cast<const float2*>(g_u + (size_t)col * DD + ofs);
            a0x += v.x; a0y += v.y;
        }
        float2 vs = *reinterpret_cast<const float2*>(g_u + (size_t)w * DD + ofs);
        a0x += vs.x; a0y += vs.y;
    }
    float ax = (a0x + a1x) + (a2x + a3x);
    float ay = (a0y + a1y) + (a2y + a3y);
    float2 h = *reinterpret_cast<const float2*>(x0 + (size_t)w * DD + ofs);
    float2 yv;
    yv.x = 0.25f * h.x + 0.75f * di * ax;
    yv.y = 0.25f * h.y + 0.75f * di * ay;
    *reinterpret_cast<float2*>(g_y + (size_t)w * DD + ofs) = yv;
    float2 xb = yv;
    if (!first) {
        float2 sv = *reinterpret_cast<const float2*>(g_S + (size_t)w * DD + ofs);
        xb.x -= 0.25f * sv.x;
        xb.y -= 0.25f * sv.y;
    }
    float2 dxv;
    dxv.x = di * xb.x;
    dxv.y = di * xb.y;
    *reinterpret_cast<float2*>(g_dx + (size_t)w * DD + ofs) = dxv;
}

// R: z[s] = l21proj(z[s] + 2*(dx[w]-dx[o])) in place, sequential z; +side partial into g_S.
// Unrolled x4: four interleaved butterfly norm chains, 1KB contiguous z per group.
__global__ __launch_bounds__(256) void kR(int n, int first) {
    int w = (blockIdx.x * 256 + threadIdx.x) >> 5;
    int lane = threadIdx.x & 31;
    if (w >= n) return;
    int base = g_r_ptr[w], end = g_r_ptr[w + 1];
    int ofs = 2 * lane;
    float2 dxw = *reinterpret_cast<const float2*>(g_dx + (size_t)w * DD + ofs);
    float sx = 0.f, sy = 0.f;
    int s = base;
    for (; s + 3 < end; s += 4) {
        int o0 = __ldg(&g_r_lst[s]);
        int o1 = __ldg(&g_r_lst[s + 1]);
        int o2 = __ldg(&g_r_lst[s + 2]);
        int o3 = __ldg(&g_r_lst[s + 3]);
        float2 d0 = *reinterpret_cast<const float2*>(g_dx + (size_t)o0 * DD + ofs);
        float2 d1 = *reinterpret_cast<const float2*>(g_dx + (size_t)o1 * DD + ofs);
        float2 d2 = *reinterpret_cast<const float2*>(g_dx + (size_t)o2 * DD + ofs);
        float2 d3 = *reinterpret_cast<const float2*>(g_dx + (size_t)o3 * DD + ofs);
        float* zp = g_z + (size_t)s * DD + ofs;
        float z0x = 2.0f * (dxw.x - d0.x), z0y = 2.0f * (dxw.y - d0.y);
        float z1x = 2.0f * (dxw.x - d1.x), z1y = 2.0f * (dxw.y - d1.y);
        float z2x = 2.0f * (dxw.x - d2.x), z2y = 2.0f * (dxw.y - d2.y);
        float z3x = 2.0f * (dxw.x - d3.x), z3y = 2.0f * (dxw.y - d3.y);
        if (!first) {
            float2 a = *reinterpret_cast<const float2*>(zp);
            float2 b = *reinterpret_cast<const float2*>(zp + DD);
            float2 c = *reinterpret_cast<const float2*>(zp + 2 * DD);
            float2 d = *reinterpret_cast<const float2*>(zp + 3 * DD);
            z0x += a.x; z0y += a.y;
            z1x += b.x; z1y += b.y;
            z2x += c.x; z2y += c.y;
            z3x += d.x; z3y += d.y;
        }
        float n0 = z0x * z0x + z0y * z0y;
        float n1 = z1x * z1x + z1y * z1y;
        float n2 = z2x * z2x + z2y * z2y;
        float n3 = z3x * z3x + z3y * z3y;
        // interleaved butterfly: 4 chains per level so SHFL latencies pipeline
        #pragma unroll
        for (int o4 = 16; o4 > 0; o4 >>= 1) {
            n0 += __shfl_xor_sync(0xffffffffu, n0, o4);
            n1 += __shfl_xor_sync(0xffffffffu, n1, o4);
            n2 += __shfl_xor_sync(0xffffffffu, n2, o4);
            n3 += __shfl_xor_sync(0xffffffffu, n3, o4);
        }
        float r0 = sqrtf(n0), r1 = sqrtf(n1), r2 = sqrtf(n2), r3 = sqrtf(n3);
        float c0 = (r0 > 0.0f) ? fminf(r0, 3.0f) / r0 : 0.0f;
        float c1 = (r1 > 0.0f) ? fminf(r1, 3.0f) / r1 : 0.0f;
        float c2 = (r2 > 0.0f) ? fminf(r2, 3.0f) / r2 : 0.0f;
        float c3 = (r3 > 0.0f) ? fminf(r3, 3.0f) / r3 : 0.0f;
        z0x *= c0; z0y *= c0;
        z1x *= c1; z1y *= c1;
        z2x *= c2; z2y *= c2;
        z3x *= c3; z3y *= c3;
        sx += (z0x + z1x) + (z2x + z3x);
        sy += (z0y + z1y) + (z2y + z3y);
        float2 t;
        t.x = z0x; t.y = z0y; *reinterpret_cast<float2*>(zp) = t;
        t.x = z1x; t.y = z1y; *reinterpret_cast<float2*>(zp + DD) = t;
        t.x = z2x; t.y = z2y; *reinterpret_cast<float2*>(zp + 2 * DD) = t;
        t.x = z3x; t.y = z3y; *reinterpret_cast<float2*>(zp + 3 * DD) = t;
    }
    for (; s < end; s++) {
        int o = __ldg(&g_r_lst[s]);
        float2 d0 = *reinterpret_cast<const float2*>(g_dx + (size_t)o * DD + ofs);
        float* zp = g_z + (size_t)s * DD + ofs;
        float zx = 2.0f * (dxw.x - d0.x), zy = 2.0f * (dxw.y - d0.y);
        if (!first) {
            float2 a = *reinterpret_cast<const float2*>(zp);
            zx += a.x; zy += a.y;
        }
        float ns = warp_sum(zx * zx + zy * zy);
        float rn = sqrtf(ns);
        float sc = (rn > 0.0f) ? fminf(rn, 3.0f) / rn : 0.0f;
        zx *= sc; zy *= sc;
        sx += zx; sy += zy;
        float2 zo; zo.x = zx; zo.y = zy;
        *reinterpret_cast<float2*>(zp) = zo;
    }
    float2 sv; sv.x = sx; sv.y = sy;
    *reinterpret_cast<float2*>(g_S + (size_t)w * DD + ofs) = sv;
}

// C2: gather projected z rows for the -side (4 independent accumulators), finalize S, xk, u
__global__ __launch_bounds__(256) void kC2(float* __restrict__ out, int n, int last) {
    int w = (blockIdx.x * 256 + threadIdx.x) >> 5;
    int lane = threadIdx.x & 31;
    if (w >= n) return;
    int base = g_c_ptr[w], end = g_c_ptr[w + 1];
    int ofs = 2 * lane;
    float s0x = 0.f, s0y = 0.f, s1x = 0.f, s1y = 0.f;
    float s2x = 0.f, s2y = 0.f, s3x = 0.f, s3y = 0.f;
    int idx = base;
    for (; idx + 3 < end; idx += 4) {
        int e0 = __ldg(&g_c_lst[idx]);
        int e1 = __ldg(&g_c_lst[idx + 1]);
        int e2 = __ldg(&g_c_lst[idx + 2]);
        int e3 = __ldg(&g_c_lst[idx + 3]);
        float2 z0 = *reinterpret_cast<const float2*>(g_z + (size_t)e0 * DD + ofs);
        float2 z1 = *reinterpret_cast<const float2*>(g_z + (size_t)e1 * DD + ofs);
        float2 z2 = *reinterpret_cast<const float2*>(g_z + (size_t)e2 * DD + ofs);
        float2 z3 = *reinterpret_cast<const float2*>(g_z + (size_t)e3 * DD + ofs);
        s0x += z0.x; s0y += z0.y;
        s1x += z1.x; s1y += z1.y;
        s2x += z2.x; s2y += z2.y;
        s3x += z3.x; s3y += z3.y;
    }
    for (; idx < end; idx++) {
        int e = __ldg(&g_c_lst[idx]);
        float2 zv = *reinterpret_cast<const float2*>(g_z + (size_t)e * DD + ofs);
        s0x += zv.x; s0y += zv.y;
    }
    float sx = (s0x + s1x) + (s2x + s3x);
    float sy = (s0y + s1y) + (s2y + s3y);
    float di = g_dis[w];
    float2 pv = *reinterpret_cast<const float2*>(g_S + (size_t)w * DD + ofs);
    float Sx = di * (pv.x - sx);
    float Sy = di * (pv.y - sy);
    float2 yv = *reinterpret_cast<const float2*>(g_y + (size_t)w * DD + ofs);
    float2 xo;
    xo.x = yv.x - 0.25f * Sx;
    xo.y = yv.y - 0.25f * Sy;
    if (last) {
        *reinterpret_cast<float2*>(out + (size_t)w * DD + ofs) = xo;
    } else {
        float2 sv; sv.x = Sx; sv.y = Sy;
        *reinterpret_cast<float2*>(g_S + (size_t)w * DD + ofs) = sv;
        float2 uv;
        uv.x = di * xo.x;
        uv.y = di * xo.y;
        *reinterpret_cast<float2*>(g_u + (size_t)w * DD + ofs) = uv;
    }
}

// ---------------- launch ----------------
extern "C" void kernel_launch(void* const* d_in, const int* in_sizes, int n_in,
                              void* d_out, int out_size) {
    (void)n_in; (void)out_size;
    const float* x0 = (const float*)d_in[0];
    const int* esrc = (const int*)d_in[1];
    const int* edst = (const int*)d_in[2];
    float* out = (float*)d_out;

    int n  = in_sizes[0] / DD;   // 50000
    int ne = in_sizes[1];        // 800000

    const int TB = 256;
    int gN  = (n + TB - 1) / TB;
    int gE  = (ne + TB - 1) / TB;
    int gWN = (n + 7) / 8;
    int nb  = (n + CH - 1) / CH;

    kInit<<<gN, TB>>>(n);
    kCount<<<gE, TB>>>(esrc, edst, ne);
    kDis<<<gN, TB>>>(n);
    kPart<<<dim3(nb, 3), CH>>>(n);
    kScanPart<<<1, 384>>>(n, nb);
    kWrite<<<dim3(nb, 3), CH>>>(n);
    kFill<<<gE, TB>>>(esrc, edst, ne);

    const int K = 10;
    for (int k = 0; k < K; k++) {
        kA<<<gWN, TB>>>(x0, n, k == 0);
        kR<<<gWN, TB>>>(n, k == 0);
        kC2<<<gWN, TB>>>(out, n, k == K - 1);
    }
}

// round 12
// speedup vs baseline: 1.0475x; 1.0475x over previous
#include <cuda_runtime.h>
#include <cstddef>

#define NN 50000
#define EE 800000
#define DD 64
#define CH 512

// ---------------- static device scratch (no allocations allowed) ----------------
__device__ float g_z[(size_t)EE * DD];     // 204.8 MB edge state (R-CSR slot order, in-place)
__device__ float g_y[NN * DD];
__device__ float g_dx[NN * DD];            // dis[i] * xbar[i]
__device__ float g_S[NN * DD];             // partial (kR) then final S (kC2)
__device__ float g_u[NN * DD];             // dis[i] * xk[i]
__device__ float g_dis[NN];

__device__ int g_adj_ptr[NN + 1];
__device__ int g_adj_cur[NN];
__device__ int g_adj_col[2 * EE];
__device__ int g_r_ptr[NN + 1];
__device__ int g_r_cur[NN];
__device__ int g_r_lst[EE];                // other endpoint (c); edge id == slot index
__device__ int g_c_ptr[NN + 1];
__device__ int g_c_cur[NN];
__device__ int g_c_lst[EE];                // R-slot of that edge
__device__ int g_cnt_adj[NN];
__device__ int g_cnt_r[NN];
__device__ int g_cnt_c[NN];
__device__ int g_part[3 * 128];

// ---------------- precompute ----------------
__global__ void kInit(int n) {
    int i = blockIdx.x * blockDim.x + threadIdx.x;
    if (i < n) { g_cnt_adj[i] = 0; g_cnt_r[i] = 0; g_cnt_c[i] = 0; }
}

__global__ void kCount(const int* __restrict__ src, const int* __restrict__ dst, int ne) {
    int e = blockIdx.x * blockDim.x + threadIdx.x;
    if (e >= ne) return;
    int s = src[e], d = dst[e];
    int r = s > d ? s : d;
    int c = s > d ? d : s;
    atomicAdd(&g_cnt_adj[s], 1);
    atomicAdd(&g_cnt_adj[d], 1);
    atomicAdd(&g_cnt_r[r], 1);
    atomicAdd(&g_cnt_c[c], 1);
}

__global__ void kDis(int n) {
    int i = blockIdx.x * blockDim.x + threadIdx.x;
    if (i >= n) return;
    float x = (float)g_cnt_adj[i] + 1.0f;
    float r = rsqrtf(x);
    r = r * (1.5f - 0.5f * x * r * r);
    g_dis[i] = r;
}

__device__ __forceinline__ const int* cnt_of(int arr) {
    return arr == 0 ? g_cnt_adj : (arr == 1 ? g_cnt_r : g_cnt_c);
}
__device__ __forceinline__ int* ptr_of(int arr) {
    return arr == 0 ? g_adj_ptr : (arr == 1 ? g_r_ptr : g_c_ptr);
}
__device__ __forceinline__ int* cur_of(int arr) {
    return arr == 0 ? g_adj_cur : (arr == 1 ? g_r_cur : g_c_cur);
}

__global__ void kPart(int n) {
    int arr = blockIdx.y;
    int b = blockIdx.x;
    int t = threadIdx.x;
    int i = b * CH + t;
    __shared__ int s[CH];
    s[t] = (i < n) ? cnt_of(arr)[i] : 0;
    __syncthreads();
    for (int off = CH / 2; off > 0; off >>= 1) {
        if (t < off) s[t] += s[t + off];
        __syncthreads();
    }
    if (t == 0) g_part[arr * 128 + b] = s[0];
}

__global__ void kScanPart(int n, int nb) {
    __shared__ int s[384];
    int t = threadIdx.x;
    int arr = t >> 7;
    int i = t & 127;
    int v = (i < nb) ? g_part[arr * 128 + i] : 0;
    s[t] = v;
    __syncthreads();
    for (int off = 1; off < 128; off <<= 1) {
        int u = (i >= off) ? s[t - off] : 0;
        __syncthreads();
        s[t] += u;
        __syncthreads();
    }
    g_part[arr * 128 + i] = s[t] - v;
    if (i == nb - 1) ptr_of(arr)[n] = s[t];
}

__global__ void kWrite(int n) {
    int arr = blockIdx.y;
    int b = blockIdx.x;
    int t = threadIdx.x;
    int i = b * CH + t;
    __shared__ int s[CH];
    int v = (i < n) ? cnt_of(arr)[i] : 0;
    s[t] = v;
    __syncthreads();
    for (int off = 1; off < CH; off <<= 1) {
        int u = (t >= off) ? s[t - off] : 0;
        __syncthreads();
        s[t] += u;
        __syncthreads();
    }
    if (i < n) {
        int excl = s[t] - v + g_part[arr * 128 + b];
        ptr_of(arr)[i] = excl;
        cur_of(arr)[i] = excl;
    }
}

__global__ void kFill(const int* __restrict__ src, const int* __restrict__ dst, int ne) {
    int e = blockIdx.x * blockDim.x + threadIdx.x;
    if (e >= ne) return;
    int s = src[e], d = dst[e];
    int p = atomicAdd(&g_adj_cur[s], 1); g_adj_col[p] = d;
    p = atomicAdd(&g_adj_cur[d], 1);     g_adj_col[p] = s;
    int r = s > d ? s : d;
    int c = s > d ? d : s;
    int slot = atomicAdd(&g_r_cur[r], 1);
    g_r_lst[slot] = c;
    p = atomicAdd(&g_c_cur[c], 1);
    g_c_lst[p] = slot;
}

// ---------------- main loop kernels ----------------

// A (warp per node, float2 per lane — exact Round-8 form):
// ax = sum_col u[col] + u[w];  y = 0.25*x0 + 0.75*dis*ax;  xbar = y - 0.25*S;  dx = dis*xbar
__global__ __launch_bounds__(256) void kA(const float* __restrict__ x0, int n, int first) {
    int w = (blockIdx.x * 256 + threadIdx.x) >> 5;
    int lane = threadIdx.x & 31;
    if (w >= n) return;
    int base = g_adj_ptr[w], end = g_adj_ptr[w + 1];
    int ofs = 2 * lane;
    float di = g_dis[w];
    float ax = 0.f, ay = 0.f;
    if (first) {
        for (int e = base; e < end; e++) {
            int col = __ldg(&g_adj_col[e]);
            float wt = __ldg(&g_dis[col]);
            float2 v = *reinterpret_cast<const float2*>(x0 + (size_t)col * DD + ofs);
            ax = fmaf(wt, v.x, ax);
            ay = fmaf(wt, v.y, ay);
        }
        float2 vs = *reinterpret_cast<const float2*>(x0 + (size_t)w * DD + ofs);
        ax = fmaf(di, vs.x, ax);
        ay = fmaf(di, vs.y, ay);
    } else {
        for (int e = base; e < end; e++) {
            int col = __ldg(&g_adj_col[e]);
            float2 v = *reinterpret_cast<const float2*>(g_u + (size_t)col * DD + ofs);
            ax += v.x;
            ay += v.y;
        }
        float2 vs = *reinterpret_cast<const float2*>(g_u + (size_t)w * DD + ofs);
        ax += vs.x;
        ay += vs.y;
    }
    float2 h = *reinterpret_cast<const float2*>(x0 + (size_t)w * DD + ofs);
    float2 yv;
    yv.x = 0.25f * h.x + 0.75f * di * ax;
    yv.y = 0.25f * h.y + 0.75f * di * ay;
    *reinterpret_cast<float2*>(g_y + (size_t)w * DD + ofs) = yv;
    float2 xb = yv;
    if (!first) {
        float2 sv = *reinterpret_cast<const float2*>(g_S + (size_t)w * DD + ofs);
        xb.x -= 0.25f * sv.x;
        xb.y -= 0.25f * sv.y;
    }
    float2 dxv;
    dxv.x = di * xb.x;
    dxv.y = di * xb.y;
    *reinterpret_cast<float2*>(g_dx + (size_t)w * DD + ofs) = dxv;
}

// R (warp per node; 8-lane groups; 4 edges per iteration):
//   z[s] = l21proj(z[s] + 2*(dx[w]-dx[o])) in place; +side partial into g_S.
//   Norm reduction = 3 SHFL levels within 8 lanes (covers all 4 edges at once).
__global__ __launch_bounds__(256) void kR(int n, int first) {
    int w = (blockIdx.x * 256 + threadIdx.x) >> 5;
    int lane = threadIdx.x & 31;
    if (w >= n) return;
    int grp = lane >> 3;               // 0..3: which edge of the group-of-4
    int sub = lane & 7;                // feature chunk: floats [sub*8, sub*8+8)
    int base = g_r_ptr[w], end = g_r_ptr[w + 1];
    const float* dwp = g_dx + (size_t)w * DD + sub * 8;
    float4 wa = *reinterpret_cast<const float4*>(dwp);
    float4 wb = *reinterpret_cast<const float4*>(dwp + 4);
    float4 sa = make_float4(0.f, 0.f, 0.f, 0.f);
    float4 sb = make_float4(0.f, 0.f, 0.f, 0.f);
    for (int s0 = base; s0 < end; s0 += 4) {
        int s = s0 + grp;
        bool act = s < end;
        int sc_ = act ? s : (end - 1);
        int o = __ldg(&g_r_lst[sc_]);
        const float* dop = g_dx + (size_t)o * DD + sub * 8;
        float4 oa = *reinterpret_cast<const float4*>(dop);
        float4 ob = *reinterpret_cast<const float4*>(dop + 4);
        float* zp = g_z + (size_t)sc_ * DD + sub * 8;
        float4 za, zb;
        za.x = 2.f * (wa.x - oa.x); za.y = 2.f * (wa.y - oa.y);
        za.z = 2.f * (wa.z - oa.z); za.w = 2.f * (wa.w - oa.w);
        zb.x = 2.f * (wb.x - ob.x); zb.y = 2.f * (wb.y - ob.y);
        zb.z = 2.f * (wb.z - ob.z); zb.w = 2.f * (wb.w - ob.w);
        if (!first) {
            float4 pa = *reinterpret_cast<const float4*>(zp);
            float4 pb = *reinterpret_cast<const float4*>(zp + 4);
            za.x += pa.x; za.y += pa.y; za.z += pa.z; za.w += pa.w;
            zb.x += pb.x; zb.y += pb.y; zb.z += pb.z; zb.w += pb.w;
        }
        float ns = za.x * za.x + za.y * za.y + za.z * za.z + za.w * za.w
                 + zb.x * zb.x + zb.y * zb.y + zb.z * zb.z + zb.w * zb.w;
        ns += __shfl_xor_sync(0xffffffffu, ns, 4);
        ns += __shfl_xor_sync(0xffffffffu, ns, 2);
        ns += __shfl_xor_sync(0xffffffffu, ns, 1);
        float rn = sqrtf(ns);
        float sc = (rn > 0.0f) ? fminf(rn, 3.0f) / rn : 0.0f;
        za.x *= sc; za.y *= sc; za.z *= sc; za.w *= sc;
        zb.x *= sc; zb.y *= sc; zb.z *= sc; zb.w *= sc;
        if (act) {
            sa.x += za.x; sa.y += za.y; sa.z += za.z; sa.w += za.w;
            sb.x += zb.x; sb.y += zb.y; sb.z += zb.z; sb.w += zb.w;
            *reinterpret_cast<float4*>(zp) = za;
            *reinterpret_cast<float4*>(zp + 4) = zb;
        }
    }
    // combine the 4 group accumulators (lanes differing in bits 3,4)
    #pragma unroll
    for (int m = 8; m <= 16; m <<= 1) {
        sa.x += __shfl_xor_sync(0xffffffffu, sa.x, m);
        sa.y += __shfl_xor_sync(0xffffffffu, sa.y, m);
        sa.z += __shfl_xor_sync(0xffffffffu, sa.z, m);
        sa.w += __shfl_xor_sync(0xffffffffu, sa.w, m);
        sb.x += __shfl_xor_sync(0xffffffffu, sb.x, m);
        sb.y += __shfl_xor_sync(0xffffffffu, sb.y, m);
        sb.z += __shfl_xor_sync(0xffffffffu, sb.z, m);
        sb.w += __shfl_xor_sync(0xffffffffu, sb.w, m);
    }
    if (grp == 0) {
        float* Sp = g_S + (size_t)w * DD + sub * 8;
        *reinterpret_cast<float4*>(Sp) = sa;       // raw +side partial
        *reinterpret_cast<float4*>(Sp + 4) = sb;
    }
}

// C2 (warp per node; 8-lane groups; 4 z-row gathers in flight):
//   gather -side z rows, finalize S, xk, u
__global__ __launch_bounds__(256) void kC2(float* __restrict__ out, int n, int last) {
    int w = (blockIdx.x * 256 + threadIdx.x) >> 5;
    int lane = threadIdx.x & 31;
    if (w >= n) return;
    int grp = lane >> 3;
    int sub = lane & 7;
    int base = g_c_ptr[w], end = g_c_ptr[w + 1];
    float4 sa = make_float4(0.f, 0.f, 0.f, 0.f);
    float4 sb = make_float4(0.f, 0.f, 0.f, 0.f);
    for (int i0 = base; i0 < end; i0 += 4) {
        int i = i0 + grp;
        if (i < end) {
            int s = __ldg(&g_c_lst[i]);
            const float* zp = g_z + (size_t)s * DD + sub * 8;
            float4 a = *reinterpret_cast<const float4*>(zp);
            float4 b = *reinterpret_cast<const float4*>(zp + 4);
            sa.x += a.x; sa.y += a.y; sa.z += a.z; sa.w += a.w;
            sb.x += b.x; sb.y += b.y; sb.z += b.z; sb.w += b.w;
        }
    }
    #pragma unroll
    for (int m = 8; m <= 16; m <<= 1) {
        sa.x += __shfl_xor_sync(0xffffffffu, sa.x, m);
        sa.y += __shfl_xor_sync(0xffffffffu, sa.y, m);
        sa.z += __shfl_xor_sync(0xffffffffu, sa.z, m);
        sa.w += __shfl_xor_sync(0xffffffffu, sa.w, m);
        sb.x += __shfl_xor_sync(0xffffffffu, sb.x, m);
        sb.y += __shfl_xor_sync(0xffffffffu, sb.y, m);
        sb.z += __shfl_xor_sync(0xffffffffu, sb.z, m);
        sb.w += __shfl_xor_sync(0xffffffffu, sb.w, m);
    }
    if (grp == 0) {
        float di = g_dis[w];
        float* Sp = g_S + (size_t)w * DD + sub * 8;
        float4 pa = *reinterpret_cast<const float4*>(Sp);
        float4 pb = *reinterpret_cast<const float4*>(Sp + 4);
        float4 Sa, Sb;
        Sa.x = di * (pa.x - sa.x); Sa.y = di * (pa.y - sa.y);
        Sa.z = di * (pa.z - sa.z); Sa.w = di * (pa.w - sa.w);
        Sb.x = di * (pb.x - sb.x); Sb.y = di * (pb.y - sb.y);
        Sb.z = di * (pb.z - sb.z); Sb.w = di * (pb.w - sb.w);
        const float* yp = g_y + (size_t)w * DD + sub * 8;
        float4 ya = *reinterpret_cast<const float4*>(yp);
        float4 yb = *reinterpret_cast<const float4*>(yp + 4);
        float4 xa, xb;
        xa.x = ya.x - 0.25f * Sa.x; xa.y = ya.y - 0.25f * Sa.y;
        xa.z = ya.z - 0.25f * Sa.z; xa.w = ya.w - 0.25f * Sa.w;
        xb.x = yb.x - 0.25f * Sb.x; xb.y = yb.y - 0.25f * Sb.y;
        xb.z = yb.z - 0.25f * Sb.z; xb.w = yb.w - 0.25f * Sb.w;
        if (last) {
            float* op = out + (size_t)w * DD + sub * 8;
            *reinterpret_cast<float4*>(op) = xa;
            *reinterpret_cast<float4*>(op + 4) = xb;
        } else {
            *reinterpret_cast<float4*>(Sp) = Sa;
            *reinterpret_cast<float4*>(Sp + 4) = Sb;
            float4 ua, ub;
            ua.x = di * xa.x; ua.y = di * xa.y; ua.z = di * xa.z; ua.w = di * xa.w;
            ub.x = di * xb.x; ub.y = di * xb.y; ub.z = di * xb.z; ub.w = di * xb.w;
            float* up = g_u + (size_t)w * DD + sub * 8;
            *reinterpret_cast<float4*>(up) = ua;
            *reinterpret_cast<float4*>(up + 4) = ub;
        }
    }
}

// ---------------- launch ----------------
extern "C" void kernel_launch(void* const* d_in, const int* in_sizes, int n_in,
                              void* d_out, int out_size) {
    (void)n_in; (void)out_size;
    const float* x0 = (const float*)d_in[0];
    const int* esrc = (const int*)d_in[1];
    const int* edst = (const int*)d_in[2];
    float* out = (float*)d_out;

    int n  = in_sizes[0] / DD;   // 50000
    int ne = in_sizes[1];        // 800000

    const int TB = 256;
    int gN  = (n + TB - 1) / TB;
    int gE  = (ne + TB - 1) / TB;
    int gWN = (n + 7) / 8;
    int nb  = (n + CH - 1) / CH;

    kInit<<<gN, TB>>>(n);
    kCount<<<gE, TB>>>(esrc, edst, ne);
    kDis<<<gN, TB>>>(n);
    kPart<<<dim3(nb, 3), CH>>>(n);
    kScanPart<<<1, 384>>>(n, nb);
    kWrite<<<dim3(nb, 3), CH>>>(n);
    kFill<<<gE, TB>>>(esrc, edst, ne);

    const int K = 10;
    for (int k = 0; k < K; k++) {
        kA<<<gWN, TB>>>(x0, n, k == 0);
        kR<<<gWN, TB>>>(n, k == 0);
        kC2<<<gWN, TB>>>(out, n, k == K - 1);
    }
}